// round 8
// baseline (speedup 1.0000x reference)
#include <cuda_runtime.h>

#define BB 8
#define HH 512
#define WW 512
#define HW (HH * WW)

#define TX 32
#define TYW 4
#define PX 2
#define PY 8
#define TILE_W (TX * PX)      // 64
#define TILE_H (TYW * PY)     // 32
#define SW 70                 // TILE_W + 6 halo cols
#define SH (TILE_H + 6)       // 38
#define SPITCH 72             // even cols [0..34], odd cols [36..70]
#define NBLOCKS ((WW / TILE_W) * (HH / TILE_H) * BB)  // 8*16*8 = 1024

__device__ unsigned long long g_pack = 0ULL;

// mismatch of one (center,neighbor) comparison across pred/target
#define M(c, v) ((int)(((c).x > (v).x) != ((c).y > (v).y)))

__global__ __launch_bounds__(TX * TYW, 7)
void census_fused(const float* __restrict__ pred, const float* __restrict__ tgt,
                  float* __restrict__ out) {
    __shared__ float2 s[SH][SPITCH];
    __shared__ int wsum[TYW];

    const int b  = blockIdx.z;
    const int x0 = blockIdx.x * TILE_W;
    const int y0 = blockIdx.y * TILE_H;
    const int tid = threadIdx.y * TX + threadIdx.x;

    const float* __restrict__ pb = pred + (size_t)b * 3 * HW;
    const float* __restrict__ tb = tgt  + (size_t)b * 3 * HW;

    // Halo load + fused RGB->gray, reflect padding. Even/odd column split
    // (branch-free index) so the PX=2 compare loads are conflict-free.
    for (int idx = tid; idx < SH * SW; idx += TX * TYW) {
        int ly = idx / SW;
        int lx = idx - ly * SW;
        int gy = y0 + ly - 3;
        gy = (gy < 0) ? -gy : ((gy >= HH) ? 2 * HH - 2 - gy : gy);
        int gx = x0 + lx - 3;
        gx = (gx < 0) ? -gx : ((gx >= WW) ? 2 * WW - 2 - gx : gx);
        int off = gy * WW + gx;
        float2 v;
        v.x = fmaf(0.299f, pb[off], fmaf(0.587f, pb[HW + off], 0.114f * pb[2 * HW + off]));
        v.y = fmaf(0.299f, tb[off], fmaf(0.587f, tb[HW + off], 0.114f * tb[2 * HW + off]));
        s[ly][(lx >> 1) + (lx & 1) * 36] = v;
    }
    __syncthreads();

    const int tx   = threadIdx.x;
    const int base = threadIdx.y * PY;

    // Centers: px0 at tile col 2tx (halo h=2tx+3, odd -> O[tx+1]),
    //          px1 at tile col 2tx+1 (h=2tx+4, even -> E[tx+2])
    float2 c0[PY], c1[PY];
#pragma unroll
    for (int k = 0; k < PY; k++) {
        c0[k] = s[base + k + 3][36 + tx + 1];
        c1[k] = s[base + k + 3][tx + 2];
    }

    int total;
    const bool interiorBlk = (blockIdx.x > 0 && blockIdx.x + 1 < gridDim.x &&
                              blockIdx.y > 0 && blockIdx.y + 1 < gridDim.y);
    if (interiorBlk) {
        // 24 forward offsets per pixel, counted x2.
        int cnt = 0;
#pragma unroll
        for (int r = 0; r < PY + 6; r++) {
            float2 vE[4], vO[4];
#pragma unroll
            for (int e = 0; e < 4; e++) {
                vE[e] = s[base + r][tx + e];
                vO[e] = s[base + r][36 + tx + e];
            }
#pragma unroll
            for (int k = 0; k < PY; k++) {
                const int dy = r - 3 - k;
                if (dy < 0 || dy > 3) continue;   // forward rows only (pruned)
                if (dy == 0) {
                    // dx = 1..3.  px0: E2,O2,E3   px1: O2,E3,O3
                    cnt += M(c0[k], vE[2]) + M(c0[k], vO[2]) + M(c0[k], vE[3]);
                    cnt += M(c1[k], vO[2]) + M(c1[k], vE[3]) + M(c1[k], vO[3]);
                } else {
                    // all dx. px0: E0,O0,E1,O1,E2,O2,E3  px1: O0,E1,O1,E2,O2,E3,O3
                    cnt += M(c0[k], vE[0]) + M(c0[k], vO[0]) + M(c0[k], vE[1])
                         + M(c0[k], vO[1]) + M(c0[k], vE[2]) + M(c0[k], vO[2])
                         + M(c0[k], vE[3]);
                    cnt += M(c1[k], vO[0]) + M(c1[k], vE[1]) + M(c1[k], vO[1])
                         + M(c1[k], vE[2]) + M(c1[k], vO[2]) + M(c1[k], vE[3])
                         + M(c1[k], vO[3]);
                }
            }
        }
        total = 2 * cnt;
    } else {
        // Exact weighted path: in-image neighbor -> fwd x2 / bwd x0;
        // out-of-image neighbor -> x1 (reflected value already in smem).
        unsigned oxm0 = 0, oxm1 = 0;
#pragma unroll
        for (int j = 0; j < 7; j++) {
            if ((unsigned)(x0 + 2 * tx + 0 + j - 3) >= WW) oxm0 |= (1u << j);
            if ((unsigned)(x0 + 2 * tx + 1 + j - 3) >= WW) oxm1 |= (1u << j);
        }

        int cnt = 0;
#pragma unroll
        for (int r = 0; r < PY + 6; r++) {
            const int oy = ((unsigned)(y0 + base + r - 3) >= HH) ? 1 : 0;
            float2 vE[4], vO[4];
#pragma unroll
            for (int e = 0; e < 4; e++) {
                vE[e] = s[base + r][tx + e];
                vO[e] = s[base + r][36 + tx + e];
            }
#pragma unroll
            for (int k = 0; k < PY; k++) {
                const int dy = r - 3 - k;
                if (dy < -3 || dy > 3) continue;  // compile-time pruned
#pragma unroll
                for (int j = 0; j < 7; j++) {
                    const int dx = j - 3;
                    if (dy == 0 && dx == 0) continue;
                    const bool fwd = (dy > 0) || (dy == 0 && dx > 0);
                    // px0: window h-offset j -> even: E[j/2], odd: O[j/2]
                    {
                        float2 v = ((j & 1) == 0) ? vE[j >> 1] : vO[j >> 1];
                        int o = oy | (int)((oxm0 >> j) & 1u);
                        int w = fwd ? (2 - o) : o;
                        cnt += M(c0[k], v) * w;
                    }
                    // px1: h-offset j+1 -> even: E[(j+1)/2], odd: O[(j+1)/2]
                    {
                        float2 v = (((j + 1) & 1) == 0) ? vE[(j + 1) >> 1] : vO[(j + 1) >> 1];
                        int o = oy | (int)((oxm1 >> j) & 1u);
                        int w = fwd ? (2 - o) : o;
                        cnt += M(c1[k], v) * w;
                    }
                }
            }
        }
        total = cnt;
    }

    // Warp + block reduction
    total = __reduce_add_sync(0xffffffffu, total);
    if (tx == 0) wsum[threadIdx.y] = total;
    __syncthreads();

    if (tid == 0) {
        int v = wsum[0] + wsum[1] + wsum[2] + wsum[3];
        // Single packed atomic: low 40 bits = count, high bits = arrival ticket.
        unsigned long long old =
            atomicAdd(&g_pack, (unsigned long long)v + (1ULL << 40));
        if ((old >> 40) == NBLOCKS - 1) {
            unsigned long long tot = (old & ((1ULL << 40) - 1)) + (unsigned long long)v;
            const double denom = 48.0 * (double)BB * (double)HW; // 100663296
            out[0] = (float)((double)tot / denom);
            g_pack = 0ULL;   // last block resets for next graph replay
        }
    }
}

extern "C" void kernel_launch(void* const* d_in, const int* in_sizes, int n_in,
                              void* d_out, int out_size) {
    const float* pred = (const float*)d_in[0];
    const float* tgt  = (const float*)d_in[1];
    float* out = (float*)d_out;
    (void)in_sizes; (void)n_in; (void)out_size;

    dim3 bdim(TX, TYW);
    dim3 gdim(WW / TILE_W, HH / TILE_H, BB);
    census_fused<<<gdim, bdim>>>(pred, tgt, out);
}

// round 9
// speedup vs baseline: 1.6607x; 1.6607x over previous
#include <cuda_runtime.h>

#define BB 8
#define HH 512
#define WW 512
#define HW (HH * WW)

#define TX 32
#define TYW 8                  // 256 threads
#define PY 8
#define TILE_H (TYW * PY)      // 64
#define SW (TX + 6)            // 38
#define SH (TILE_H + 6)        // 70
#define NBLOCKS ((WW / TX) * (HH / TILE_H) * BB)   // 16*8*8 = 1024

__device__ unsigned long long g_pack = 0ULL;

__global__ __launch_bounds__(TX * TYW, 6)
void census_fused(const float* __restrict__ pred, const float* __restrict__ tgt,
                  float* __restrict__ out) {
    __shared__ float2 s[SH][SW];     // (pred_gray, tgt_gray)
    __shared__ int wsum[TYW];

    const int b  = blockIdx.z;
    const int x0 = blockIdx.x * TX;
    const int y0 = blockIdx.y * TILE_H;
    const int tid = threadIdx.y * TX + threadIdx.x;

    const float* __restrict__ pb = pred + (size_t)b * 3 * HW;
    const float* __restrict__ tb = tgt  + (size_t)b * 3 * HW;

    // Halo load + fused RGB->gray, reflect padding (no edge repeat)
    for (int idx = tid; idx < SH * SW; idx += TX * TYW) {
        int ly = idx / SW;
        int lx = idx - ly * SW;
        int gy = y0 + ly - 3;
        gy = (gy < 0) ? -gy : ((gy >= HH) ? 2 * HH - 2 - gy : gy);
        int gx = x0 + lx - 3;
        gx = (gx < 0) ? -gx : ((gx >= WW) ? 2 * WW - 2 - gx : gx);
        int off = gy * WW + gx;
        float2 v;
        v.x = fmaf(0.299f, pb[off], fmaf(0.587f, pb[HW + off], 0.114f * pb[2 * HW + off]));
        v.y = fmaf(0.299f, tb[off], fmaf(0.587f, tb[HW + off], 0.114f * tb[2 * HW + off]));
        s[ly][lx] = v;
    }
    __syncthreads();

    const int tx   = threadIdx.x;
    const int base = threadIdx.y * PY;

    float cp[PY], ct[PY];
#pragma unroll
    for (int k = 0; k < PY; k++) {
        float2 c = s[base + k + 3][tx + 3];
        cp[k] = c.x; ct[k] = c.y;
    }

    // Uniform full 48-neighbor census diff (reflect already in smem):
    // per window row, load 7 float2 once, reuse across all centers covering it.
    int cnt = 0;
#pragma unroll
    for (int r = 0; r < PY + 6; r++) {
        float2 v[7];
#pragma unroll
        for (int j = 0; j < 7; j++) v[j] = s[base + r][tx + j];
#pragma unroll
        for (int k = 0; k < PY; k++) {
            const int dy = r - 3 - k;              // compile-time constant
            if (dy < -3 || dy > 3) continue;       // pruned
#pragma unroll
            for (int j = 0; j < 7; j++) {
                if (dy == 0 && j == 3) continue;   // center excluded
                cnt += ((cp[k] > v[j].x) != (ct[k] > v[j].y)) ? 1 : 0;
            }
        }
    }

    // Warp + block reduction
    cnt = __reduce_add_sync(0xffffffffu, cnt);
    if (tx == 0) wsum[threadIdx.y] = cnt;
    __syncthreads();

    if (tid == 0) {
        int v = 0;
#pragma unroll
        for (int w = 0; w < TYW; w++) v += wsum[w];
        // Packed atomic: low 40 bits = mismatch count, high bits = arrivals.
        unsigned long long old =
            atomicAdd(&g_pack, (unsigned long long)v + (1ULL << 40));
        if ((old >> 40) == NBLOCKS - 1) {
            unsigned long long tot = (old & ((1ULL << 40) - 1)) + (unsigned long long)v;
            const double denom = 48.0 * (double)BB * (double)HW;  // 100663296
            out[0] = (float)((double)tot / denom);
            g_pack = 0ULL;    // reset for next graph replay
        }
    }
}

extern "C" void kernel_launch(void* const* d_in, const int* in_sizes, int n_in,
                              void* d_out, int out_size) {
    const float* pred = (const float*)d_in[0];
    const float* tgt  = (const float*)d_in[1];
    float* out = (float*)d_out;
    (void)in_sizes; (void)n_in; (void)out_size;

    dim3 bdim(TX, TYW);
    dim3 gdim(WW / TX, HH / TILE_H, BB);
    census_fused<<<gdim, bdim>>>(pred, tgt, out);
}